// round 2
// baseline (speedup 1.0000x reference)
#include <cuda_runtime.h>
#include <cuda_bf16.h>

#define NQ      14
#define NSTATES (1 << NQ)          // 16384
#define THREADS 512
#define ITERS   (NSTATES / (THREADS * 4))   // 8

// One block per batch row, 512 threads, 8 fully-unrolled float4-pair iterations.
// Sign structure of the Pauli-Z diagonals factored by n-bit field:
//   n = it*2048 + tid*4 + j
//   bits 0..1   (j)   -> D0 (bit0), D1 (bit1) with fixed intra-float4 signs
//   bits 2..10  (tid) -> sign constant per thread: applied to S once at the end
//   bits 11..13 (it)  -> compile-time +- on accumulation of s (free FADD modifier)
__global__ __launch_bounds__(THREADS)
void measurement_kernel(const float* __restrict__ sr,
                        const float* __restrict__ si,
                        float* __restrict__ out)
{
    const int row = blockIdx.x;
    const int tid = threadIdx.x;

    const float4* __restrict__ sr4 =
        reinterpret_cast<const float4*>(sr + (size_t)row * NSTATES);
    const float4* __restrict__ si4 =
        reinterpret_cast<const float4*>(si + (size_t)row * NSTATES);

    float D0 = 0.f, D1 = 0.f, S = 0.f;
    float A11 = 0.f, A12 = 0.f, A13 = 0.f;

#pragma unroll
    for (int it = 0; it < ITERS; ++it) {
        const int idx = it * THREADS + tid;
        const float4 a = __ldcs(&sr4[idx]);   // streaming: evict-first, touched once
        const float4 b = __ldcs(&si4[idx]);

        const float p0 = a.x * a.x + b.x * b.x;
        const float p1 = a.y * a.y + b.y * b.y;
        const float p2 = a.z * a.z + b.z * b.z;
        const float p3 = a.w * a.w + b.w * b.w;

        const float s01 = p0 + p1;
        const float s23 = p2 + p3;
        const float s   = s01 + s23;

        D0 += (p0 - p1) + (p2 - p3);   // n-bit 0
        D1 += s01 - s23;               // n-bit 1
        S  += s;                       // n-bits 2..10 handled via per-thread sign

        // n-bits 11..13: it is compile-time constant under full unroll
        A11 += (it & 1) ? -s : s;
        A12 += (it & 2) ? -s : s;
        A13 += (it & 4) ? -s : s;
    }

    // Expand to 14 per-qubit partials. Qubit q <-> n-bit b = 13 - q (q0 = MSB).
    float v[NQ];
    v[0] = A13;  // b=13
    v[1] = A12;  // b=12
    v[2] = A11;  // b=11
#pragma unroll
    for (int q = 3; q <= 11; ++q) {
        const int b   = 13 - q;               // 10..2
        const int bit = (tid >> (b - 2)) & 1; // n-bit b == tid bit (b-2)
        v[q] = bit ? -S : S;
    }
    v[12] = D1;  // b=1
    v[13] = D0;  // b=0

    // Warp butterfly reduction of all 14 values.
#pragma unroll
    for (int q = 0; q < NQ; ++q) {
#pragma unroll
        for (int off = 16; off > 0; off >>= 1)
            v[q] += __shfl_xor_sync(0xffffffffu, v[q], off);
    }

    __shared__ float red[THREADS / 32][NQ];
    const int warp = tid >> 5;
    const int lane = tid & 31;
    if (lane == 0) {
#pragma unroll
        for (int q = 0; q < NQ; ++q) red[warp][q] = v[q];
    }
    __syncthreads();

    if (tid < NQ) {
        float r = 0.f;
#pragma unroll
        for (int w = 0; w < THREADS / 32; ++w) r += red[w][tid];
        out[(size_t)row * NQ + tid] = r;
    }
}

extern "C" void kernel_launch(void* const* d_in, const int* in_sizes, int n_in,
                              void* d_out, int out_size)
{
    const float* sr = (const float*)d_in[0];  // state_real [4096, 16384]
    const float* si = (const float*)d_in[1];  // state_imag [4096, 16384]
    float* out = (float*)d_out;               // [4096, 14]

    const int batch = in_sizes[0] / NSTATES;  // 4096
    measurement_kernel<<<batch, THREADS>>>(sr, si, out);
}

// round 3
// speedup vs baseline: 1.0028x; 1.0028x over previous
#include <cuda_runtime.h>
#include <cuda_bf16.h>

#define NQ      14
#define NSTATES (1 << NQ)          // 16384
#define THREADS 256
#define ELEMS_PER_THREAD 8
#define ITERS   (NSTATES / (THREADS * ELEMS_PER_THREAD))   // 8

// One block per batch row, 256 threads. Each thread handles 8 contiguous
// elements per iteration (2 consecutive float4 per array) so a warp issues
// 1KB contiguous per array per step. Fully unrolled; signs factored by n-bit:
//   n = it*2048 + tid*8 + j
//   bits 0..2   (j)   -> D0/D1/D2 with fixed intra-thread sign trees
//   bits 3..10  (tid) -> sign constant per thread, applied to S at the end
//   bits 11..13 (it)  -> compile-time +- under full unroll (A11..A13)
__global__ __launch_bounds__(THREADS)
void measurement_kernel(const float* __restrict__ sr,
                        const float* __restrict__ si,
                        float* __restrict__ out)
{
    const int row = blockIdx.x;
    const int tid = threadIdx.x;

    const float4* __restrict__ sr4 =
        reinterpret_cast<const float4*>(sr + (size_t)row * NSTATES);
    const float4* __restrict__ si4 =
        reinterpret_cast<const float4*>(si + (size_t)row * NSTATES);

    float D0 = 0.f, D1 = 0.f, D2 = 0.f, S = 0.f;
    float A11 = 0.f, A12 = 0.f, A13 = 0.f;

#pragma unroll
    for (int it = 0; it < ITERS; ++it) {
        const int base = (it * THREADS + tid) * 2;   // float4 index; thread owns 2 consecutive
        const float4 a0 = sr4[base + 0];
        const float4 a1 = sr4[base + 1];
        const float4 b0 = si4[base + 0];
        const float4 b1 = si4[base + 1];

        const float p0 = a0.x * a0.x + b0.x * b0.x;
        const float p1 = a0.y * a0.y + b0.y * b0.y;
        const float p2 = a0.z * a0.z + b0.z * b0.z;
        const float p3 = a0.w * a0.w + b0.w * b0.w;
        const float p4 = a1.x * a1.x + b1.x * b1.x;
        const float p5 = a1.y * a1.y + b1.y * b1.y;
        const float p6 = a1.z * a1.z + b1.z * b1.z;
        const float p7 = a1.w * a1.w + b1.w * b1.w;

        const float s01 = p0 + p1, s23 = p2 + p3, s45 = p4 + p5, s67 = p6 + p7;
        const float s0123 = s01 + s23, s4567 = s45 + s67;
        const float s = s0123 + s4567;

        D0 += ((p0 - p1) + (p2 - p3)) + ((p4 - p5) + (p6 - p7));  // n-bit 0
        D1 += (s01 - s23) + (s45 - s67);                          // n-bit 1
        D2 += s0123 - s4567;                                      // n-bit 2
        S  += s;                                                  // n-bits 3..10

        // n-bits 11..13: it is compile-time constant under full unroll
        A11 += (it & 1) ? -s : s;
        A12 += (it & 2) ? -s : s;
        A13 += (it & 4) ? -s : s;
    }

    // Expand to 14 per-qubit partials. Qubit q <-> n-bit b = 13 - q (q0 = MSB).
    float v[NQ];
    v[0] = A13;  // b=13
    v[1] = A12;  // b=12
    v[2] = A11;  // b=11
#pragma unroll
    for (int q = 3; q <= 10; ++q) {
        const int b   = 13 - q;               // 10..3
        const int bit = (tid >> (b - 3)) & 1; // n-bit b == tid bit (b-3)
        v[q] = bit ? -S : S;
    }
    v[11] = D2;  // b=2
    v[12] = D1;  // b=1
    v[13] = D0;  // b=0

    // Warp butterfly reduction of all 14 values.
#pragma unroll
    for (int q = 0; q < NQ; ++q) {
#pragma unroll
        for (int off = 16; off > 0; off >>= 1)
            v[q] += __shfl_xor_sync(0xffffffffu, v[q], off);
    }

    __shared__ float red[THREADS / 32][NQ];
    const int warp = tid >> 5;
    const int lane = tid & 31;
    if (lane == 0) {
#pragma unroll
        for (int q = 0; q < NQ; ++q) red[warp][q] = v[q];
    }
    __syncthreads();

    if (tid < NQ) {
        float r = 0.f;
#pragma unroll
        for (int w = 0; w < THREADS / 32; ++w) r += red[w][tid];
        out[(size_t)row * NQ + tid] = r;
    }
}

extern "C" void kernel_launch(void* const* d_in, const int* in_sizes, int n_in,
                              void* d_out, int out_size)
{
    const float* sr = (const float*)d_in[0];  // state_real [4096, 16384]
    const float* si = (const float*)d_in[1];  // state_imag [4096, 16384]
    float* out = (float*)d_out;               // [4096, 14]

    const int batch = in_sizes[0] / NSTATES;  // 4096
    measurement_kernel<<<batch, THREADS>>>(sr, si, out);
}